// round 1
// baseline (speedup 1.0000x reference)
#include <cuda_runtime.h>

#define D_FEAT   128
#define K_DIM    256
#define OUT_DIM  128
#define MAX_NODES 100000

#define GROWS    64      // rows per GEMM block
#define GTHREADS 256     // 8 warps

// Scratch for h = A @ x  (allocation-free: __device__ global)
__device__ float g_h[(size_t)MAX_NODES * D_FEAT];

typedef unsigned long long u64;

__device__ __forceinline__ u64 pack2(float lo, float hi) {
    u64 r; asm("mov.b64 %0, {%1,%2};" : "=l"(r) : "f"(lo), "f"(hi)); return r;
}
__device__ __forceinline__ u64 fma2(u64 a, u64 b, u64 c) {
    u64 d; asm("fma.rn.f32x2 %0, %1, %2, %3;" : "=l"(d) : "l"(a), "l"(b), "l"(c)); return d;
}
__device__ __forceinline__ float2 unpack2(u64 v) {
    float2 f; asm("mov.b64 {%0,%1}, %2;" : "=f"(f.x), "=f"(f.y) : "l"(v)); return f;
}

// ---------------------------------------------------------------------------
// Kernel 1: zero the h scratch (float4 stores)
// ---------------------------------------------------------------------------
__global__ void zero_h_kernel(int n_f4) {
    int i = blockIdx.x * blockDim.x + threadIdx.x;
    if (i < n_f4) {
        float4 z = make_float4(0.f, 0.f, 0.f, 0.f);
        ((float4*)g_h)[i] = z;
    }
}

// ---------------------------------------------------------------------------
// Kernel 2: COO SpMM scatter.  One warp per edge:
//   h[row] += val * x[col]   (128 floats, 4 per lane, atomicAdd)
// x and h both fit in L2, so gathers/atomics are L2-resident.
// ---------------------------------------------------------------------------
__global__ void spmm_kernel(const float* __restrict__ x,
                            const int*   __restrict__ rows,
                            const int*   __restrict__ cols,
                            const float* __restrict__ vals,
                            int n_edges) {
    int warp = (blockIdx.x * blockDim.x + threadIdx.x) >> 5;
    int lane = threadIdx.x & 31;
    if (warp >= n_edges) return;

    int   r = rows[warp];
    int   c = cols[warp];
    float v = vals[warp];

    float4 xv = ((const float4*)(x + (size_t)c * D_FEAT))[lane];
    float* hp = g_h + (size_t)r * D_FEAT + lane * 4;
    atomicAdd(hp + 0, v * xv.x);
    atomicAdd(hp + 1, v * xv.y);
    atomicAdd(hp + 2, v * xv.z);
    atomicAdd(hp + 3, v * xv.w);
}

// ---------------------------------------------------------------------------
// Kernel 3: out = relu(h @ W[:128] + x @ W[128:]) == relu([h|x] @ W)
// Tile: 64 rows x 128 cols per block, K = 256.
// smem: W  (256*128 f32 = 128 KB)  +  A tile (64*256 f32 = 64 KB) = 192 KB
// Each warp: 8 rows.  Each lane: cols [4*lane, 4*lane+4)  -> 16 f32x2 accums.
// fp32 math done with packed fma.rn.f32x2 (2x scalar FFMA throughput).
// ---------------------------------------------------------------------------
__global__ __launch_bounds__(GTHREADS, 1)
void gemm_relu_kernel(const float* __restrict__ x,
                      const float* __restrict__ W,
                      float* __restrict__ out,
                      int n_nodes) {
    extern __shared__ float smem[];
    float* Ws = smem;                        // [256][128]
    float* As = smem + K_DIM * OUT_DIM;      // [64][256]

    const int tid  = threadIdx.x;
    const int row0 = blockIdx.x * GROWS;

    // ---- stage W into smem (32 float4 per thread) ----
    {
        const float4* Wg = (const float4*)W;
        float4*       Wd = (float4*)Ws;
#pragma unroll
        for (int i = 0; i < (K_DIM * OUT_DIM / 4) / GTHREADS; i++)
            Wd[tid + i * GTHREADS] = Wg[tid + i * GTHREADS];
    }

    // ---- stage A tile: A[r][k] = (k < 128) ? h[row][k] : x[row][k-128] ----
    {
        for (int i = tid; i < GROWS * 64; i += GTHREADS) {
            int r  = i >> 6;       // local row
            int q  = i & 63;       // float4 index in [0,64)
            int gr = row0 + r;
            float4 v;
            if (gr < n_nodes) {
                if (q < 32) v = ((const float4*)(g_h + (size_t)gr * D_FEAT))[q];
                else        v = ((const float4*)(x   + (size_t)gr * D_FEAT))[q - 32];
            } else {
                v = make_float4(0.f, 0.f, 0.f, 0.f);
            }
            ((float4*)(As + r * K_DIM))[q] = v;
        }
    }
    __syncthreads();

    const int warp = tid >> 5;
    const int lane = tid & 31;
    const float* Arow = As + (warp * 8) * K_DIM;
    const float* Wl   = Ws + lane * 4;

    u64 acc[8][2];
#pragma unroll
    for (int r = 0; r < 8; r++) { acc[r][0] = 0ULL; acc[r][1] = 0ULL; }

#pragma unroll 4
    for (int k = 0; k < K_DIM; k += 2) {
        // W rows k and k+1: lane's 4 cols, loaded as two b64 pairs each
        ulonglong2 w0 = *(const ulonglong2*)(Wl + (size_t)k * OUT_DIM);
        ulonglong2 w1 = *(const ulonglong2*)(Wl + (size_t)(k + 1) * OUT_DIM);
#pragma unroll
        for (int r = 0; r < 8; r++) {
            float2 a  = *(const float2*)(Arow + r * K_DIM + k);  // broadcast LDS.64
            u64    a0 = pack2(a.x, a.x);
            u64    a1 = pack2(a.y, a.y);
            acc[r][0] = fma2(a0, w0.x, acc[r][0]);
            acc[r][1] = fma2(a0, w0.y, acc[r][1]);
            acc[r][0] = fma2(a1, w1.x, acc[r][0]);
            acc[r][1] = fma2(a1, w1.y, acc[r][1]);
        }
    }

    // ---- relu + store ----
#pragma unroll
    for (int r = 0; r < 8; r++) {
        int gr = row0 + warp * 8 + r;
        if (gr < n_nodes) {
            float2 p0 = unpack2(acc[r][0]);
            float2 p1 = unpack2(acc[r][1]);
            float4 o;
            o.x = fmaxf(p0.x, 0.f);
            o.y = fmaxf(p0.y, 0.f);
            o.z = fmaxf(p1.x, 0.f);
            o.w = fmaxf(p1.y, 0.f);
            ((float4*)(out + (size_t)gr * OUT_DIM))[lane] = o;
        }
    }
}

// ---------------------------------------------------------------------------
// Launch: inputs are [x, adj_rows, adj_cols, adj_vals, W]; output fp32 [N,128]
// ---------------------------------------------------------------------------
extern "C" void kernel_launch(void* const* d_in, const int* in_sizes, int n_in,
                              void* d_out, int out_size) {
    const float* x    = (const float*)d_in[0];
    const int*   rows = (const int*)  d_in[1];
    const int*   cols = (const int*)  d_in[2];
    const float* vals = (const float*)d_in[3];
    const float* W    = (const float*)d_in[4];
    float*       out  = (float*)d_out;

    const int n_nodes = in_sizes[0] / D_FEAT;
    const int n_edges = in_sizes[1];

    // 1) zero h
    int n_f4 = n_nodes * (D_FEAT / 4);
    zero_h_kernel<<<(n_f4 + 255) / 256, 256>>>(n_f4);

    // 2) edge scatter (one warp per edge)
    long long total_threads = (long long)n_edges * 32;
    int spmm_blocks = (int)((total_threads + 255) / 256);
    spmm_kernel<<<spmm_blocks, 256>>>(x, rows, cols, vals, n_edges);

    // 3) fused dense GEMM + relu
    const int smem_bytes = (K_DIM * OUT_DIM + GROWS * K_DIM) * (int)sizeof(float); // 196608
    cudaFuncSetAttribute(gemm_relu_kernel,
                         cudaFuncAttributeMaxDynamicSharedMemorySize, smem_bytes);
    int gemm_blocks = (n_nodes + GROWS - 1) / GROWS;
    gemm_relu_kernel<<<gemm_blocks, GTHREADS, smem_bytes>>>(x, W, out, n_nodes);
}

// round 2
// speedup vs baseline: 1.3353x; 1.3353x over previous
#include <cuda_runtime.h>

#define D_FEAT    128
#define K_DIM     256
#define OUT_DIM   128
#define MAX_NODES 100000
#define MAX_EDGES 600000

#define GROWS    64      // rows per GEMM block
#define GTHREADS 256     // 8 warps

#define SCAN_BLK 1024
#define MAX_NB   128     // ceil(100001/1024) = 98

// ---- device scratch (allocation-free) ----
__device__ float g_h[(size_t)MAX_NODES * D_FEAT];
__device__ int   g_cnt[MAX_NODES];
__device__ int   g_off[MAX_NODES + 1];
__device__ int   g_cur[MAX_NODES];
__device__ int   g_bsum[MAX_NB];
__device__ int2  g_edge[MAX_EDGES];   // .x = col, .y = float bits of val

typedef unsigned long long u64;

__device__ __forceinline__ u64 pack2(float lo, float hi) {
    u64 r; asm("mov.b64 %0, {%1,%2};" : "=l"(r) : "f"(lo), "f"(hi)); return r;
}
__device__ __forceinline__ u64 fma2(u64 a, u64 b, u64 c) {
    u64 d; asm("fma.rn.f32x2 %0, %1, %2, %3;" : "=l"(d) : "l"(a), "l"(b), "l"(c)); return d;
}
__device__ __forceinline__ float2 unpack2(u64 v) {
    float2 f; asm("mov.b64 {%0,%1}, %2;" : "=f"(f.x), "=f"(f.y) : "l"(v)); return f;
}

// ---------------------------------------------------------------------------
// CSR build: zero counts -> histogram -> 3-phase scan -> scatter permute
// ---------------------------------------------------------------------------
__global__ void zero_cnt_kernel(int n) {
    int i = blockIdx.x * blockDim.x + threadIdx.x;
    if (i < n) g_cnt[i] = 0;
}

__global__ void hist_kernel(const int* __restrict__ rows, int n_edges) {
    int i = blockIdx.x * blockDim.x + threadIdx.x;
    if (i < n_edges) atomicAdd(&g_cnt[rows[i]], 1);
}

// Phase 1: per-block totals of counts
__global__ void scan_reduce_kernel(int n) {
    __shared__ int s[SCAN_BLK];
    int t = threadIdx.x;
    int i = blockIdx.x * SCAN_BLK + t;
    s[t] = (i < n) ? g_cnt[i] : 0;
    __syncthreads();
    for (int off = SCAN_BLK / 2; off > 0; off >>= 1) {
        if (t < off) s[t] += s[t + off];
        __syncthreads();
    }
    if (t == 0) g_bsum[blockIdx.x] = s[0];
}

// Phase 2: single-block exclusive scan of block totals (nb <= 1024)
__global__ void scan_bsum_kernel(int nb) {
    __shared__ int s[SCAN_BLK];
    int t = threadIdx.x;
    int v = (t < nb) ? g_bsum[t] : 0;
    s[t] = v;
    __syncthreads();
    for (int off = 1; off < SCAN_BLK; off <<= 1) {
        int add = (t >= off) ? s[t - off] : 0;
        __syncthreads();
        s[t] += add;
        __syncthreads();
    }
    if (t < nb) g_bsum[t] = s[t] - v;   // exclusive
}

// Phase 3: per-block exclusive scan + base; write offsets + cursors
__global__ void scan_write_kernel(int n, int n_edges) {
    __shared__ int s[SCAN_BLK];
    int t = threadIdx.x;
    int i = blockIdx.x * SCAN_BLK + t;
    int v = (i < n) ? g_cnt[i] : 0;
    s[t] = v;
    __syncthreads();
    for (int off = 1; off < SCAN_BLK; off <<= 1) {
        int add = (t >= off) ? s[t - off] : 0;
        __syncthreads();
        s[t] += add;
        __syncthreads();
    }
    if (i < n) {
        int o = g_bsum[blockIdx.x] + s[t] - v;   // exclusive
        g_off[i] = o;
        g_cur[i] = o;
    }
    if (i == 0) g_off[n] = n_edges;
}

__global__ void scatter_kernel(const int*   __restrict__ rows,
                               const int*   __restrict__ cols,
                               const float* __restrict__ vals,
                               int n_edges) {
    int i = blockIdx.x * blockDim.x + threadIdx.x;
    if (i < n_edges) {
        int r = rows[i];
        int p = atomicAdd(&g_cur[r], 1);
        g_edge[p] = make_int2(cols[i], __float_as_int(vals[i]));
    }
}

// ---------------------------------------------------------------------------
// CSR SpMM: one warp per row, register accumulation, single store.
// Also writes zeros for empty rows (replaces zero_h).
// ---------------------------------------------------------------------------
__global__ void spmm_csr_kernel(const float* __restrict__ x, int n_nodes) {
    int row  = (blockIdx.x * blockDim.x + threadIdx.x) >> 5;
    int lane = threadIdx.x & 31;
    if (row >= n_nodes) return;

    int e0 = g_off[row];
    int e1 = g_off[row + 1];

    float4 acc = make_float4(0.f, 0.f, 0.f, 0.f);
    for (int e = e0; e < e1; ++e) {
        int2  ev = g_edge[e];                 // broadcast LDG.64
        float v  = __int_as_float(ev.y);
        float4 xv = ((const float4*)(x + (size_t)ev.x * D_FEAT))[lane];
        acc.x = fmaf(v, xv.x, acc.x);
        acc.y = fmaf(v, xv.y, acc.y);
        acc.z = fmaf(v, xv.z, acc.z);
        acc.w = fmaf(v, xv.w, acc.w);
    }
    ((float4*)(g_h + (size_t)row * D_FEAT))[lane] = acc;
}

// ---------------------------------------------------------------------------
// out = relu([h|x] @ W)   64x128 tile, K=256, packed fma.rn.f32x2
// ---------------------------------------------------------------------------
__global__ __launch_bounds__(GTHREADS, 1)
void gemm_relu_kernel(const float* __restrict__ x,
                      const float* __restrict__ W,
                      float* __restrict__ out,
                      int n_nodes) {
    extern __shared__ float smem[];
    float* Ws = smem;                        // [256][128]
    float* As = smem + K_DIM * OUT_DIM;      // [64][256]

    const int tid  = threadIdx.x;
    const int row0 = blockIdx.x * GROWS;

    {
        const float4* Wg = (const float4*)W;
        float4*       Wd = (float4*)Ws;
#pragma unroll
        for (int i = 0; i < (K_DIM * OUT_DIM / 4) / GTHREADS; i++)
            Wd[tid + i * GTHREADS] = Wg[tid + i * GTHREADS];
    }

    {
        for (int i = tid; i < GROWS * 64; i += GTHREADS) {
            int r  = i >> 6;
            int q  = i & 63;
            int gr = row0 + r;
            float4 v;
            if (gr < n_nodes) {
                if (q < 32) v = ((const float4*)(g_h + (size_t)gr * D_FEAT))[q];
                else        v = ((const float4*)(x   + (size_t)gr * D_FEAT))[q - 32];
            } else {
                v = make_float4(0.f, 0.f, 0.f, 0.f);
            }
            ((float4*)(As + r * K_DIM))[q] = v;
        }
    }
    __syncthreads();

    const int warp = tid >> 5;
    const int lane = tid & 31;
    const float* Arow = As + (warp * 8) * K_DIM;
    const float* Wl   = Ws + lane * 4;

    u64 acc[8][2];
#pragma unroll
    for (int r = 0; r < 8; r++) { acc[r][0] = 0ULL; acc[r][1] = 0ULL; }

#pragma unroll 4
    for (int k = 0; k < K_DIM; k += 2) {
        ulonglong2 w0 = *(const ulonglong2*)(Wl + (size_t)k * OUT_DIM);
        ulonglong2 w1 = *(const ulonglong2*)(Wl + (size_t)(k + 1) * OUT_DIM);
#pragma unroll
        for (int r = 0; r < 8; r++) {
            float2 a  = *(const float2*)(Arow + r * K_DIM + k);
            u64    a0 = pack2(a.x, a.x);
            u64    a1 = pack2(a.y, a.y);
            acc[r][0] = fma2(a0, w0.x, acc[r][0]);
            acc[r][1] = fma2(a0, w0.y, acc[r][1]);
            acc[r][0] = fma2(a1, w1.x, acc[r][0]);
            acc[r][1] = fma2(a1, w1.y, acc[r][1]);
        }
    }

#pragma unroll
    for (int r = 0; r < 8; r++) {
        int gr = row0 + warp * 8 + r;
        if (gr < n_nodes) {
            float2 p0 = unpack2(acc[r][0]);
            float2 p1 = unpack2(acc[r][1]);
            float4 o;
            o.x = fmaxf(p0.x, 0.f);
            o.y = fmaxf(p0.y, 0.f);
            o.z = fmaxf(p1.x, 0.f);
            o.w = fmaxf(p1.y, 0.f);
            ((float4*)(out + (size_t)gr * OUT_DIM))[lane] = o;
        }
    }
}

// ---------------------------------------------------------------------------
extern "C" void kernel_launch(void* const* d_in, const int* in_sizes, int n_in,
                              void* d_out, int out_size) {
    const float* x    = (const float*)d_in[0];
    const int*   rows = (const int*)  d_in[1];
    const int*   cols = (const int*)  d_in[2];
    const float* vals = (const float*)d_in[3];
    const float* W    = (const float*)d_in[4];
    float*       out  = (float*)d_out;

    const int n_nodes = in_sizes[0] / D_FEAT;
    const int n_edges = in_sizes[1];
    const int nb      = (n_nodes + SCAN_BLK - 1) / SCAN_BLK;

    // --- CSR build ---
    zero_cnt_kernel<<<(n_nodes + 255) / 256, 256>>>(n_nodes);
    hist_kernel<<<(n_edges + 255) / 256, 256>>>(rows, n_edges);
    scan_reduce_kernel<<<nb, SCAN_BLK>>>(n_nodes);
    scan_bsum_kernel<<<1, SCAN_BLK>>>(nb);
    scan_write_kernel<<<nb, SCAN_BLK>>>(n_nodes, n_edges);
    scatter_kernel<<<(n_edges + 255) / 256, 256>>>(rows, cols, vals, n_edges);

    // --- SpMM (warp per row) ---
    long long spmm_threads = (long long)n_nodes * 32;
    spmm_csr_kernel<<<(int)((spmm_threads + 255) / 256), 256>>>(x, n_nodes);

    // --- fused dense GEMM + relu ---
    const int smem_bytes = (K_DIM * OUT_DIM + GROWS * K_DIM) * (int)sizeof(float);
    cudaFuncSetAttribute(gemm_relu_kernel,
                         cudaFuncAttributeMaxDynamicSharedMemorySize, smem_bytes);
    int gemm_blocks = (n_nodes + GROWS - 1) / GROWS;
    gemm_relu_kernel<<<gemm_blocks, GTHREADS, smem_bytes>>>(x, W, out, n_nodes);
}

// round 4
// speedup vs baseline: 2.7338x; 2.0473x over previous
#include <cuda_runtime.h>
#include <cuda_bf16.h>
#include <cstdint>

#define D_FEAT    128
#define K_DIM     256
#define OUT_DIM   128
#define MAX_NODES 100000
#define MAX_EDGES 600000
#define SCAN_BLK  1024

// GEMM tile
#define TM   128
#define TN   128
#define CK   128                  // K per chunk (2 chunks: h then x)
#define LDA  136                  // padded row length in bf16 (272 B stride)
#define GT   256                  // 8 warps

// ---- device scratch (allocation-free) ----
__device__ float g_h[(size_t)MAX_NODES * D_FEAT];
__device__ int   g_cnt[MAX_NODES];
__device__ int   g_off[MAX_NODES + 1];
__device__ int   g_cur[MAX_NODES];
__device__ int   g_bsum[128];
__device__ int2  g_edge[MAX_EDGES];
// Pre-built bf16 hi/lo smem images of B (B[n][k] = W[k][n]), per chunk:
// layout [chunk][part(hi,lo)][n=128][k=LDA] halves; pads stay zero (bss init)
__device__ uint4 g_Bimg4[2 * 4352];   // 2 chunks x 69632 B

// ============================ PTX helpers =================================
__device__ __forceinline__ uint32_t smem_u32(const void* p) {
    uint32_t a;
    asm("{ .reg .u64 t; cvta.to.shared.u64 t, %1; cvt.u32.u64 %0, t; }" : "=r"(a) : "l"(p));
    return a;
}
__device__ __forceinline__ void ldsm4(uint32_t* r, uint32_t addr) {
    asm volatile("ldmatrix.sync.aligned.m8n8.x4.shared.b16 {%0,%1,%2,%3}, [%4];"
                 : "=r"(r[0]), "=r"(r[1]), "=r"(r[2]), "=r"(r[3]) : "r"(addr));
}
__device__ __forceinline__ void mma_bf16(float* d, const uint32_t* a,
                                         uint32_t b0, uint32_t b1) {
    asm volatile(
        "mma.sync.aligned.m16n8k16.row.col.f32.bf16.bf16.f32 "
        "{%0,%1,%2,%3}, {%4,%5,%6,%7}, {%8,%9}, {%0,%1,%2,%3};"
        : "+f"(d[0]), "+f"(d[1]), "+f"(d[2]), "+f"(d[3])
        : "r"(a[0]), "r"(a[1]), "r"(a[2]), "r"(a[3]), "r"(b0), "r"(b1));
}
// pack {lo: convert(x), hi: convert(y)} -> cvt d, y, x
__device__ __forceinline__ uint32_t bf16x2(float y, float x) {
    uint32_t r; asm("cvt.rn.bf16x2.f32 %0, %1, %2;" : "=r"(r) : "f"(y), "f"(x)); return r;
}

// ========================= CSR build kernels ===============================
__global__ void zero_cnt_kernel(int n, int n_edges) {
    int i = blockIdx.x * blockDim.x + threadIdx.x;
    if (i < n) g_cnt[i] = 0;
    if (i == 0) g_off[n] = n_edges;
}
__global__ void hist_kernel(const int* __restrict__ rows, int n_edges) {
    int i = blockIdx.x * blockDim.x + threadIdx.x;
    if (i < n_edges) atomicAdd(&g_cnt[rows[i]], 1);
}
__global__ void scan_reduce_kernel(int n) {
    __shared__ int s[SCAN_BLK];
    int t = threadIdx.x;
    int i = blockIdx.x * SCAN_BLK + t;
    s[t] = (i < n) ? g_cnt[i] : 0;
    __syncthreads();
    for (int off = SCAN_BLK / 2; off > 0; off >>= 1) {
        if (t < off) s[t] += s[t + off];
        __syncthreads();
    }
    if (t == 0) g_bsum[blockIdx.x] = s[0];
}
// fused: block base (sum of earlier block totals) + local exclusive scan
__global__ void scan_write_kernel(int n, int nb) {
    __shared__ int s[SCAN_BLK];
    int t = threadIdx.x;
    int bv = (t < nb && t < (int)blockIdx.x) ? g_bsum[t] : 0;
    s[t] = bv;
    __syncthreads();
    for (int off = SCAN_BLK / 2; off > 0; off >>= 1) {
        if (t < off) s[t] += s[t + off];
        __syncthreads();
    }
    int base = s[0];
    __syncthreads();
    int i = blockIdx.x * SCAN_BLK + t;
    int v = (i < n) ? g_cnt[i] : 0;
    s[t] = v;
    __syncthreads();
    for (int off = 1; off < SCAN_BLK; off <<= 1) {
        int add = (t >= off) ? s[t - off] : 0;
        __syncthreads();
        s[t] += add;
        __syncthreads();
    }
    if (i < n) {
        int o = base + s[t] - v;
        g_off[i] = o;
        g_cur[i] = o;
    }
}
__global__ void scatter_kernel(const int* __restrict__ rows,
                               const int* __restrict__ cols,
                               const float* __restrict__ vals,
                               int n_edges) {
    int i = blockIdx.x * blockDim.x + threadIdx.x;
    if (i < n_edges) {
        int r = rows[i];
        int p = atomicAdd(&g_cur[r], 1);
        g_edge[p] = make_int2(cols[i], __float_as_int(vals[i]));
    }
}

// ============================ CSR SpMM =====================================
__global__ void spmm_csr_kernel(const float* __restrict__ x, int n_nodes) {
    int row  = (blockIdx.x * blockDim.x + threadIdx.x) >> 5;
    int lane = threadIdx.x & 31;
    if (row >= n_nodes) return;

    int e  = g_off[row];
    int e1 = g_off[row + 1];

    float4 a0 = make_float4(0.f, 0.f, 0.f, 0.f);
    float4 a1 = make_float4(0.f, 0.f, 0.f, 0.f);
    for (; e + 2 <= e1; e += 2) {
        int2 ev0 = g_edge[e];
        int2 ev1 = g_edge[e + 1];
        float4 x0 = ((const float4*)(x + (size_t)ev0.x * D_FEAT))[lane];
        float4 x1 = ((const float4*)(x + (size_t)ev1.x * D_FEAT))[lane];
        float v0 = __int_as_float(ev0.y);
        float v1 = __int_as_float(ev1.y);
        a0.x = fmaf(v0, x0.x, a0.x); a0.y = fmaf(v0, x0.y, a0.y);
        a0.z = fmaf(v0, x0.z, a0.z); a0.w = fmaf(v0, x0.w, a0.w);
        a1.x = fmaf(v1, x1.x, a1.x); a1.y = fmaf(v1, x1.y, a1.y);
        a1.z = fmaf(v1, x1.z, a1.z); a1.w = fmaf(v1, x1.w, a1.w);
    }
    if (e < e1) {
        int2 ev = g_edge[e];
        float4 xv = ((const float4*)(x + (size_t)ev.x * D_FEAT))[lane];
        float v = __int_as_float(ev.y);
        a0.x = fmaf(v, xv.x, a0.x); a0.y = fmaf(v, xv.y, a0.y);
        a0.z = fmaf(v, xv.z, a0.z); a0.w = fmaf(v, xv.w, a0.w);
    }
    float4 acc = make_float4(a0.x + a1.x, a0.y + a1.y, a0.z + a1.z, a0.w + a1.w);
    ((float4*)(g_h + (size_t)row * D_FEAT))[lane] = acc;
}

// ======================= B (=W^T) bf16 hi/lo prep ==========================
__global__ void bprep_kernel(const float* __restrict__ W) {
    int i = blockIdx.x * blockDim.x + threadIdx.x;    // over 2*128*128
    if (i >= 2 * 128 * 128) return;
    int c = i >> 14;
    int r = i & 16383;
    int k = r >> 7;          // 0..127
    int n = r & 127;
    float w = W[(size_t)(c * 128 + k) * OUT_DIM + n];
    __nv_bfloat16 hb = __float2bfloat16(w);
    float fh = __bfloat162float(hb);
    __nv_bfloat16 lb = __float2bfloat16(w - fh);
    __nv_bfloat16* img = (__nv_bfloat16*)g_Bimg4;
    // [chunk][part][n][LDA]
    img[(((size_t)c * 2 + 0) * 128 + n) * LDA + k] = hb;
    img[(((size_t)c * 2 + 1) * 128 + n) * LDA + k] = lb;
}

// ============ mma.sync bf16 3-pass GEMM: out = relu([h|x] @ W) =============
// smem: A hi/lo images [128][LDA] bf16 (34816 B each), then B hi/lo same.
#define SM_A   0
#define SM_PART 34816
#define SM_B   69632
#define SM_TOTAL 139264

__global__ __launch_bounds__(GT, 1)
void gemm_mma_kernel(const float* __restrict__ x,
                     float* __restrict__ out,
                     int n_nodes) {
    extern __shared__ char smem[];
    const uint32_t sbase = smem_u32(smem);
    const int tid  = threadIdx.x;
    const int wid  = tid >> 5;
    const int lane = tid & 31;
    const int wm   = wid >> 1;       // 0..3  (32-row strip)
    const int wn   = wid & 1;        // 0..1  (64-col strip)
    const int row0 = blockIdx.x * TM;

    // ldmatrix lane base pointers (byte smem addresses)
    uint32_t pA[2], pB[4];
#pragma unroll
    for (int mf = 0; mf < 2; mf++)
        pA[mf] = sbase + SM_A
               + (uint32_t)((wm * 32 + mf * 16 + (lane & 15)) * (LDA * 2))
               + (uint32_t)((lane >> 4) << 4);
#pragma unroll
    for (int p = 0; p < 4; p++)
        pB[p] = sbase + SM_B
              + (uint32_t)((wn * 64 + p * 16 + (lane & 7) + ((lane >> 4) << 3)) * (LDA * 2))
              + (uint32_t)((lane & 8) << 1);

    float acc[2][8][4];
#pragma unroll
    for (int mf = 0; mf < 2; mf++)
#pragma unroll
        for (int nf = 0; nf < 8; nf++)
#pragma unroll
            for (int q = 0; q < 4; q++) acc[mf][nf][q] = 0.f;

    for (int c = 0; c < 2; c++) {
        // ---- stage A chunk (split fp32 -> bf16 hi/lo) ----
        const float* src = (c == 0) ? g_h : x;
#pragma unroll
        for (int j = 0; j < (TM * CK / 4) / GT; j++) {       // 16 iters
            int i  = tid + j * GT;
            int r  = i >> 5;          // 32 float4 per row
            int kq = i & 31;
            int gr = row0 + r;
            float4 v = make_float4(0.f, 0.f, 0.f, 0.f);
            if (gr < n_nodes) v = ((const float4*)(src + (size_t)gr * D_FEAT))[kq];
            uint32_t h01 = bf16x2(v.y, v.x);
            uint32_t h23 = bf16x2(v.w, v.z);
            float fx = __uint_as_float(h01 << 16);
            float fy = __uint_as_float(h01 & 0xffff0000u);
            float fz = __uint_as_float(h23 << 16);
            float fw = __uint_as_float(h23 & 0xffff0000u);
            uint32_t l01 = bf16x2(v.y - fy, v.x - fx);
            uint32_t l23 = bf16x2(v.w - fw, v.z - fz);
            char* dst = smem + SM_A + r * (LDA * 2) + kq * 8;
            *(uint2*)dst               = make_uint2(h01, h23);
            *(uint2*)(dst + SM_PART)   = make_uint2(l01, l23);
        }
        // ---- copy prebuilt B chunk image (hi+lo contiguous) ----
        {
            const uint4* sB = g_Bimg4 + (size_t)c * 4352;
            uint4* dB = (uint4*)(smem + SM_B);
#pragma unroll
            for (int j = tid; j < 4352; j += GT) dB[j] = sB[j];
        }
        __syncthreads();

        // ---- MMA mainloop: 8 k-steps of 16 ----
#pragma unroll
        for (int ks = 0; ks < CK / 16; ks++) {
            const uint32_t k0b = (uint32_t)(ks << 5);
            uint32_t Ah[2][4], Al[2][4];
#pragma unroll
            for (int mf = 0; mf < 2; mf++) {
                ldsm4(Ah[mf], pA[mf] + k0b);
                ldsm4(Al[mf], pA[mf] + SM_PART + k0b);
            }
            uint32_t Bh[4][4], Bl[4][4];
#pragma unroll
            for (int p = 0; p < 4; p++) {
                ldsm4(Bh[p], pB[p] + k0b);
                ldsm4(Bl[p], pB[p] + SM_PART + k0b);
            }
#pragma unroll
            for (int mf = 0; mf < 2; mf++)
#pragma unroll
                for (int p = 0; p < 4; p++) {
                    mma_bf16(acc[mf][2 * p],     Ah[mf], Bh[p][0], Bh[p][1]);
                    mma_bf16(acc[mf][2 * p + 1], Ah[mf], Bh[p][2], Bh[p][3]);
                    mma_bf16(acc[mf][2 * p],     Al[mf], Bh[p][0], Bh[p][1]);
                    mma_bf16(acc[mf][2 * p + 1], Al[mf], Bh[p][2], Bh[p][3]);
                    mma_bf16(acc[mf][2 * p],     Ah[mf], Bl[p][0], Bl[p][1]);
                    mma_bf16(acc[mf][2 * p + 1], Ah[mf], Bl[p][2], Bl[p][3]);
                }
        }
        __syncthreads();   // before restaging smem for next chunk
    }

    // ---- epilogue: relu + store ----
#pragma unroll
    for (int mf = 0; mf < 2; mf++) {
        int gr0 = row0 + wm * 32 + mf * 16 + (lane >> 2);
#pragma unroll
        for (int nf = 0; nf < 8; nf++) {
            int col = wn * 64 + (nf >> 1) * 16 + (nf & 1) * 8 + (lane & 3) * 2;
            float* a = acc[mf][nf];
            if (gr0 < n_nodes) {
                float2 o0 = make_float2(fmaxf(a[0], 0.f), fmaxf(a[1], 0.f));
                *(float2*)(out + (size_t)gr0 * OUT_DIM + col) = o0;
            }
            if (gr0 + 8 < n_nodes) {
                float2 o1 = make_float2(fmaxf(a[2], 0.f), fmaxf(a[3], 0.f));
                *(float2*)(out + (size_t)(gr0 + 8) * OUT_DIM + col) = o1;
            }
        }
    }
}

// ============================== launch =====================================
extern "C" void kernel_launch(void* const* d_in, const int* in_sizes, int n_in,
                              void* d_out, int out_size) {
    const float* x    = (const float*)d_in[0];
    const int*   rows = (const int*)  d_in[1];
    const int*   cols = (const int*)  d_in[2];
    const float* vals = (const float*)d_in[3];
    const float* W    = (const float*)d_in[4];
    float*       out  = (float*)d_out;

    const int n_nodes = in_sizes[0] / D_FEAT;
    const int n_edges = in_sizes[1];
    const int nb      = (n_nodes + SCAN_BLK - 1) / SCAN_BLK;

    // B prep (graph-data independent)
    bprep_kernel<<<(2 * 128 * 128 + 255) / 256, 256>>>(W);

    // CSR build
    zero_cnt_kernel<<<(n_nodes + 255) / 256, 256>>>(n_nodes, n_edges);
    hist_kernel<<<(n_edges + 255) / 256, 256>>>(rows, n_edges);
    scan_reduce_kernel<<<nb, SCAN_BLK>>>(n_nodes);
    scan_write_kernel<<<nb, SCAN_BLK>>>(n_nodes, nb);
    scatter_kernel<<<(n_edges + 255) / 256, 256>>>(rows, cols, vals, n_edges);

    // SpMM (warp per row)
    long long spmm_threads = (long long)n_nodes * 32;
    spmm_csr_kernel<<<(int)((spmm_threads + 255) / 256), 256>>>(x, n_nodes);

    // mma.sync bf16 3-pass GEMM + relu
    cudaFuncSetAttribute(gemm_mma_kernel,
                         cudaFuncAttributeMaxDynamicSharedMemorySize, SM_TOTAL);
    int gemm_blocks = (n_nodes + TM - 1) / TM;
    gemm_mma_kernel<<<gemm_blocks, GT, SM_TOTAL>>>(x, out, n_nodes);
}